// round 14
// baseline (speedup 1.0000x reference)
#include <cuda_runtime.h>
#include <cuda_bf16.h>
#include <cstdint>

#define T_MAX 8192
#define K_IN  4096
#define K_BYTES (K_IN * 2)
#define N_OUT 4096
#define RANK  8

#define BM 256
#define BN 128
#define BKB 256                  // K bytes per stage (128 bf16)
#define NKT (K_IN * 2 / BKB)     // 32
#define STAGES 2
#define SROW 272                 // 256B data + 16B pad (conflict-free LDSM)
#define STAGE_BYTES ((BM + BN) * SROW)       // 104448
#define SMEM_TOTAL  (STAGES * STAGE_BYTES)   // 208896 -> occ 1 (512 thr)

// Scratch (no allocations allowed)
__device__ __nv_bfloat16 g_xh[(size_t)T_MAX * K_IN];
__device__ float  g_xs[T_MAX];
__device__ float  g_xa[(size_t)T_MAX * RANK];
__device__ __nv_bfloat16 g_wh[(size_t)N_OUT * K_IN];

static __device__ __forceinline__ uint32_t bf16pair(int a, int b) {
    __nv_bfloat16 ba = __float2bfloat16((float)a);
    __nv_bfloat16 bb = __float2bfloat16((float)b);
    return (uint32_t)__bfloat16_as_ushort(ba) |
           ((uint32_t)__bfloat16_as_ushort(bb) << 16);
}

// ---------------------------------------------------------------------------
// Kernel 1: merged prework (even blocks: quant+LoRA-A row; odd: pack W)
// ---------------------------------------------------------------------------
__global__ __launch_bounds__(256) void prework_kernel(const float* __restrict__ x,
                                                      const float* __restrict__ A,
                                                      const void* __restrict__ w) {
    int sub = blockIdx.x >> 1;
    int tid = threadIdx.x;

    if (blockIdx.x & 1) {
        size_t gid = (size_t)sub * 512 + tid * 2;
        int dv = ((const int*)w)[gid];
        int small = (dv >= -200 && dv <= 200) ? 1 : 0;
        int mode32 = __syncthreads_and(small);
#pragma unroll
        for (int u = 0; u < 2; u++) {
            size_t g = gid + u;
            int q0, q1, q2, q3;
            if (mode32) {
                int4 v = ((const int4*)w)[g];
                q0 = v.x; q1 = v.y; q2 = v.z; q3 = v.w;
            } else {
                char4 v = ((const char4*)w)[g];
                q0 = v.x; q1 = v.y; q2 = v.z; q3 = v.w;
            }
            uint2 o;
            o.x = bf16pair(q0, q1);
            o.y = bf16pair(q2, q3);
            ((uint2*)g_wh)[g] = o;
        }
        return;
    }

    int row = sub;
    int lane = tid & 31, wid = tid >> 5;
    const float4* xr = (const float4*)(x + (size_t)row * K_IN);
    float4 v[4];
    float m = 0.f;
#pragma unroll
    for (int i = 0; i < 4; i++) {
        v[i] = xr[tid + 256 * i];
        m = fmaxf(m, fmaxf(fmaxf(fabsf(v[i].x), fabsf(v[i].y)),
                           fmaxf(fabsf(v[i].z), fabsf(v[i].w))));
    }
    __shared__ float red[8];
    __shared__ float lred[8][RANK];
#pragma unroll
    for (int o = 16; o > 0; o >>= 1) m = fmaxf(m, __shfl_xor_sync(0xffffffffu, m, o));
    if (lane == 0) red[wid] = m;

    float acc[RANK];
#pragma unroll
    for (int r = 0; r < RANK; r++) acc[r] = 0.f;
#pragma unroll
    for (int i = 0; i < 4; i++) {
        int k = (tid + 256 * i) * 4;
#pragma unroll
        for (int r = 0; r < RANK; r++) {
            float4 av = *(const float4*)(A + (size_t)r * K_IN + k);
            acc[r] = fmaf(v[i].x, av.x, acc[r]);
            acc[r] = fmaf(v[i].y, av.y, acc[r]);
            acc[r] = fmaf(v[i].z, av.z, acc[r]);
            acc[r] = fmaf(v[i].w, av.w, acc[r]);
        }
    }
#pragma unroll
    for (int r = 0; r < RANK; r++) {
#pragma unroll
        for (int o = 16; o > 0; o >>= 1)
            acc[r] += __shfl_xor_sync(0xffffffffu, acc[r], o);
    }
    if (lane == 0) {
#pragma unroll
        for (int r = 0; r < RANK; r++) lred[wid][r] = acc[r];
    }
    __syncthreads();
    if (tid < 32) {
        float mm = (tid < 8) ? red[tid] : 0.f;
#pragma unroll
        for (int o = 4; o > 0; o >>= 1) mm = fmaxf(mm, __shfl_xor_sync(0xffffffffu, mm, o));
        if (tid == 0) red[0] = mm;
    }
    if (tid < RANK) {
        float s = 0.f;
#pragma unroll
        for (int w8 = 0; w8 < 8; w8++) s += lred[w8][tid];
        g_xa[(size_t)row * RANK + tid] = s;
    }
    __syncthreads();
    m = red[0];
    float scale = m * (1.0f / 127.0f);
    float inv   = 1.0f / fmaxf(scale, 1e-12f);
    if (tid == 0) g_xs[row] = scale;

    uint2* qr = (uint2*)(g_xh + (size_t)row * K_IN);
#pragma unroll
    for (int i = 0; i < 4; i++) {
        int qx = __float2int_rn(v[i].x * inv);
        int qy = __float2int_rn(v[i].y * inv);
        int qz = __float2int_rn(v[i].z * inv);
        int qw = __float2int_rn(v[i].w * inv);
        qx = max(-127, min(127, qx)); qy = max(-127, min(127, qy));
        qz = max(-127, min(127, qz)); qw = max(-127, min(127, qw));
        uint2 o;
        o.x = bf16pair(qx, qy);
        o.y = bf16pair(qz, qw);
        qr[tid + 256 * i] = o;
    }
}

// ---------------------------------------------------------------------------
// Kernel 2: bf16 HMMA GEMM, 256x128 tile, BK=128, 2-stage, frag prefetch
// ---------------------------------------------------------------------------
__device__ __forceinline__ void cp_async16(uint32_t dst, const void* src) {
    asm volatile("cp.async.cg.shared.global [%0], [%1], 16;\n" :: "r"(dst), "l"(src));
}
__device__ __forceinline__ void mma_bf16(float* c, const uint32_t* a, const uint32_t* b) {
    asm volatile(
        "mma.sync.aligned.m16n8k16.row.col.f32.bf16.bf16.f32 "
        "{%0,%1,%2,%3}, {%4,%5,%6,%7}, {%8,%9}, {%0,%1,%2,%3};"
        : "+f"(c[0]), "+f"(c[1]), "+f"(c[2]), "+f"(c[3])
        : "r"(a[0]), "r"(a[1]), "r"(a[2]), "r"(a[3]), "r"(b[0]), "r"(b[1]));
}
__device__ __forceinline__ void ldsm_x4(uint32_t& r0, uint32_t& r1,
                                        uint32_t& r2, uint32_t& r3, uint32_t addr) {
    asm volatile("ldmatrix.sync.aligned.m8n8.x4.shared.b16 {%0,%1,%2,%3}, [%4];"
                 : "=r"(r0), "=r"(r1), "=r"(r2), "=r"(r3) : "r"(addr));
}

__global__ __launch_bounds__(512, 1)
void gemm_kernel(const float* __restrict__ wscale,
                 const float* __restrict__ lora_b,
                 float* __restrict__ out) {
    extern __shared__ __align__(128) char smem[];
    uint32_t sbase = (uint32_t)__cvta_generic_to_shared(smem);

    int tid  = threadIdx.x;
    int wid  = tid >> 5;
    int lane = tid & 31;
    int gid  = lane >> 2;
    int tid4 = lane & 3;
    int wm = wid & 3;          // 4 warps along M (64 rows each)
    int wn = wid >> 2;         // 4 warps along N (32 cols each)
    int bm = blockIdx.y, bn = blockIdx.x;

    const char* Aglob = (const char*)(g_xh + (size_t)(bm * BM) * K_IN);
    const char* Bglob = (const char*)(g_wh + (size_t)(bn * BN) * K_IN);

    int a_row  = ((lane >> 3) & 1) * 8 + (lane & 7);
    int a_koff = (lane >> 4) * 16;
    int b_row  = (lane >> 4) * 8 + (lane & 7);
    int b_koff = ((lane >> 3) & 1) * 16;

    float c[4][4][4];
#pragma unroll
    for (int mf = 0; mf < 4; mf++)
#pragma unroll
        for (int nf = 0; nf < 4; nf++)
#pragma unroll
            for (int i = 0; i < 4; i++) c[mf][nf][i] = 0.f;

    // stage: [A 256 rows x 256B][B 128 rows x 256B]; 6144 16B-chunks / 512 thr
#define LOAD_TILE(t)                                                              \
    do {                                                                          \
        int _s  = (t) & 1;                                                        \
        int _k0 = (t) * BKB;                                                      \
        uint32_t _sa = sbase + _s * STAGE_BYTES;                                  \
        uint32_t _sb = _sa + BM * SROW;                                           \
        _Pragma("unroll")                                                         \
        for (int _u = 0; _u < 8; _u++) {                                          \
            int _idx = tid + 512 * _u;                                            \
            int _row = _idx >> 4;                                                 \
            int _ch  = (_idx & 15) * 16;                                          \
            cp_async16(_sa + _row * SROW + _ch,                                   \
                       Aglob + (size_t)_row * K_BYTES + _k0 + _ch);               \
        }                                                                         \
        _Pragma("unroll")                                                         \
        for (int _u = 0; _u < 4; _u++) {                                          \
            int _idx = tid + 512 * _u;                                            \
            int _row = _idx >> 4;                                                 \
            int _ch  = (_idx & 15) * 16;                                          \
            cp_async16(_sb + _row * SROW + _ch,                                   \
                       Bglob + (size_t)_row * K_BYTES + _k0 + _ch);               \
        }                                                                         \
        asm volatile("cp.async.commit_group;\n");                                 \
    } while (0)

    LOAD_TILE(0); LOAD_TILE(1);

    uint32_t a[2][4][4];   // A frag double buffer across ks
    uint32_t b[2][4];      // B frag double buffer across np

#define LD_A(dst, aB, ko)                                                         \
    do {                                                                          \
        _Pragma("unroll")                                                         \
        for (int _mf = 0; _mf < 4; _mf++)                                         \
            ldsm_x4(a[dst][_mf][0], a[dst][_mf][1], a[dst][_mf][2],               \
                    a[dst][_mf][3], (aB) + _mf * 16 * SROW + (ko));               \
    } while (0)
#define LD_B(dst, bB, np, ko)                                                     \
    do {                                                                          \
        ldsm_x4(b[dst][0], b[dst][1], b[dst][2], b[dst][3],                       \
                (bB) + (np) * 16 * SROW + (ko));                                  \
    } while (0)

    for (int kt = 0; kt < NKT; kt++) {
        asm volatile("cp.async.wait_group 1;\n");
        __syncthreads();

        int buf = kt & 1;
        uint32_t aBase = sbase + buf * STAGE_BYTES + (wm * 64 + a_row) * SROW + a_koff;
        uint32_t bBase = sbase + buf * STAGE_BYTES + BM * SROW + (wn * 32 + b_row) * SROW + b_koff;

        LD_A(0, aBase, 0);
        LD_B(0, bBase, 0, 0);
#pragma unroll
        for (int ks = 0; ks < 8; ks++) {
            int ko  = ks * 32;
            int cab = ks & 1;          // current A buffer
            // prefetch next-ks A while current MMAs run
            if (ks < 7) LD_A(cab ^ 1, aBase, ko + 32);
#pragma unroll
            for (int np = 0; np < 2; np++) {
                int cbb = np & 1;      // current B buffer (0 then 1)
                // prefetch next B frag (np=1 of this ks, or np=0 of next ks)
                if (np == 0) {
                    LD_B(1, bBase, 1, ko);
                } else if (ks < 7) {
                    LD_B(0, bBase, 0, ko + 32);
                }
#pragma unroll
                for (int mf = 0; mf < 4; mf++) {
                    mma_bf16(c[mf][2 * np + 0], a[cab][mf], &b[cbb][0]);
                    mma_bf16(c[mf][2 * np + 1], a[cab][mf], &b[cbb][2]);
                }
            }
        }

        __syncthreads();   // all warps done reading buf -> safe to refill
        if (kt + 2 < NKT) {
            LOAD_TILE(kt + 2);
        } else {
            asm volatile("cp.async.commit_group;\n");
        }
    }
    asm volatile("cp.async.wait_group 0;\n");
    __syncthreads();

    // --- epilogue: reuse smem stage 0 ---
    float* s_xs = (float*)smem;            // [BM]
    float* s_ws = s_xs + BM;               // [BN]
    float* s_xa = s_ws + BN;               // [BM*RANK]
    float* s_lb = s_xa + BM * RANK;        // [BN*RANK]

    if (tid < BM) s_xs[tid] = g_xs[bm * BM + tid];
    if (tid < BN) s_ws[tid] = wscale[bn * BN + tid];
    for (int i = tid; i < BM * RANK / 4; i += 512)
        ((float4*)s_xa)[i] = ((const float4*)(g_xa + (size_t)bm * BM * RANK))[i];
    for (int i = tid; i < BN * RANK / 4; i += 512)
        ((float4*)s_lb)[i] = ((const float4*)(lora_b + (size_t)bn * BN * RANK))[i];
    __syncthreads();

#pragma unroll
    for (int mf = 0; mf < 4; mf++) {
#pragma unroll
        for (int nf = 0; nf < 4; nf++) {
            int rl0 = wm * 64 + mf * 16 + gid;
            int cl  = wn * 32 + nf * 8 + tid4 * 2;
            float ws0 = s_ws[cl], ws1 = s_ws[cl + 1];
#pragma unroll
            for (int h = 0; h < 2; h++) {
                int rl = rl0 + h * 8;
                float xs = s_xs[rl];
                float l0 = 0.f, l1 = 0.f;
#pragma unroll
                for (int r = 0; r < RANK; r++) {
                    float xv = s_xa[rl * RANK + r];
                    l0 = fmaf(xv, s_lb[cl * RANK + r], l0);
                    l1 = fmaf(xv, s_lb[(cl + 1) * RANK + r], l1);
                }
                float o0 = c[mf][nf][h * 2 + 0] * xs * ws0 + l0;
                float o1 = c[mf][nf][h * 2 + 1] * xs * ws1 + l1;
                size_t grow = (size_t)(bm * BM + rl);
                int    gcol = bn * BN + cl;
                *(float2*)(out + grow * N_OUT + gcol) = make_float2(o0, o1);
            }
        }
    }
}

// ---------------------------------------------------------------------------
extern "C" void kernel_launch(void* const* d_in, const int* in_sizes, int n_in,
                              void* d_out, int out_size) {
    const float*  x      = (const float*)d_in[0];
    const void*   w_raw  = d_in[1];
    const float*  wscale = (const float*)d_in[2];
    const float*  lora_a = (const float*)d_in[3];
    const float*  lora_b = (const float*)d_in[4];
    float* out = (float*)d_out;

    int T = in_sizes[0] / K_IN;  // 8192

    cudaFuncSetAttribute(gemm_kernel,
                         cudaFuncAttributeMaxDynamicSharedMemorySize, SMEM_TOTAL);

    prework_kernel<<<2 * T, 256>>>(x, lora_a, w_raw);
    dim3 g3(N_OUT / BN, T / BM);
    gemm_kernel<<<g3, 512, SMEM_TOTAL>>>(wscale, lora_b, out);
}

// round 15
// speedup vs baseline: 1.1697x; 1.1697x over previous
#include <cuda_runtime.h>
#include <cuda_bf16.h>
#include <cstdint>

#define T_MAX 8192
#define K_IN  4096
#define K_BYTES (K_IN * 2)
#define N_OUT 4096
#define RANK  8

#define BM 256
#define BN 128
#define NKT (K_IN / 64)          // 64 k-tiles of 64 bf16 (128B)
#define STAGES 3
#define SROW 144                 // 128B data + 16B pad (conflict-free LDSM)
#define STAGE_BYTES ((BM + BN) * SROW)       // 55296
#define SMEM_TOTAL  (STAGES * STAGE_BYTES)   // 165888 -> occ 1 (512 thr)

// Scratch (no allocations allowed)
__device__ __nv_bfloat16 g_xh[(size_t)T_MAX * K_IN];
__device__ float  g_xs[T_MAX];
__device__ float  g_xa[(size_t)T_MAX * RANK];
__device__ __nv_bfloat16 g_wh[(size_t)N_OUT * K_IN];

static __device__ __forceinline__ uint32_t bf16pair(int a, int b) {
    __nv_bfloat16 ba = __float2bfloat16((float)a);
    __nv_bfloat16 bb = __float2bfloat16((float)b);
    return (uint32_t)__bfloat16_as_ushort(ba) |
           ((uint32_t)__bfloat16_as_ushort(bb) << 16);
}

// ---------------------------------------------------------------------------
// Kernel 1: merged prework (even blocks: quant+LoRA-A row; odd: pack W)
// ---------------------------------------------------------------------------
__global__ __launch_bounds__(256) void prework_kernel(const float* __restrict__ x,
                                                      const float* __restrict__ A,
                                                      const void* __restrict__ w) {
    int sub = blockIdx.x >> 1;
    int tid = threadIdx.x;

    if (blockIdx.x & 1) {
        size_t gid = (size_t)sub * 512 + tid * 2;
        int dv = ((const int*)w)[gid];
        int small = (dv >= -200 && dv <= 200) ? 1 : 0;
        int mode32 = __syncthreads_and(small);
#pragma unroll
        for (int u = 0; u < 2; u++) {
            size_t g = gid + u;
            int q0, q1, q2, q3;
            if (mode32) {
                int4 v = ((const int4*)w)[g];
                q0 = v.x; q1 = v.y; q2 = v.z; q3 = v.w;
            } else {
                char4 v = ((const char4*)w)[g];
                q0 = v.x; q1 = v.y; q2 = v.z; q3 = v.w;
            }
            uint2 o;
            o.x = bf16pair(q0, q1);
            o.y = bf16pair(q2, q3);
            ((uint2*)g_wh)[g] = o;
        }
        return;
    }

    int row = sub;
    int lane = tid & 31, wid = tid >> 5;
    const float4* xr = (const float4*)(x + (size_t)row * K_IN);
    float4 v[4];
    float m = 0.f;
#pragma unroll
    for (int i = 0; i < 4; i++) {
        v[i] = xr[tid + 256 * i];
        m = fmaxf(m, fmaxf(fmaxf(fabsf(v[i].x), fabsf(v[i].y)),
                           fmaxf(fabsf(v[i].z), fabsf(v[i].w))));
    }
    __shared__ float red[8];
    __shared__ float lred[8][RANK];
#pragma unroll
    for (int o = 16; o > 0; o >>= 1) m = fmaxf(m, __shfl_xor_sync(0xffffffffu, m, o));
    if (lane == 0) red[wid] = m;

    float acc[RANK];
#pragma unroll
    for (int r = 0; r < RANK; r++) acc[r] = 0.f;
#pragma unroll
    for (int i = 0; i < 4; i++) {
        int k = (tid + 256 * i) * 4;
#pragma unroll
        for (int r = 0; r < RANK; r++) {
            float4 av = *(const float4*)(A + (size_t)r * K_IN + k);
            acc[r] = fmaf(v[i].x, av.x, acc[r]);
            acc[r] = fmaf(v[i].y, av.y, acc[r]);
            acc[r] = fmaf(v[i].z, av.z, acc[r]);
            acc[r] = fmaf(v[i].w, av.w, acc[r]);
        }
    }
#pragma unroll
    for (int r = 0; r < RANK; r++) {
#pragma unroll
        for (int o = 16; o > 0; o >>= 1)
            acc[r] += __shfl_xor_sync(0xffffffffu, acc[r], o);
    }
    if (lane == 0) {
#pragma unroll
        for (int r = 0; r < RANK; r++) lred[wid][r] = acc[r];
    }
    __syncthreads();
    if (tid < 32) {
        float mm = (tid < 8) ? red[tid] : 0.f;
#pragma unroll
        for (int o = 4; o > 0; o >>= 1) mm = fmaxf(mm, __shfl_xor_sync(0xffffffffu, mm, o));
        if (tid == 0) red[0] = mm;
    }
    if (tid < RANK) {
        float s = 0.f;
#pragma unroll
        for (int w8 = 0; w8 < 8; w8++) s += lred[w8][tid];
        g_xa[(size_t)row * RANK + tid] = s;
    }
    __syncthreads();
    m = red[0];
    float scale = m * (1.0f / 127.0f);
    float inv   = 1.0f / fmaxf(scale, 1e-12f);
    if (tid == 0) g_xs[row] = scale;

    uint2* qr = (uint2*)(g_xh + (size_t)row * K_IN);
#pragma unroll
    for (int i = 0; i < 4; i++) {
        int qx = __float2int_rn(v[i].x * inv);
        int qy = __float2int_rn(v[i].y * inv);
        int qz = __float2int_rn(v[i].z * inv);
        int qw = __float2int_rn(v[i].w * inv);
        qx = max(-127, min(127, qx)); qy = max(-127, min(127, qy));
        qz = max(-127, min(127, qz)); qw = max(-127, min(127, qw));
        uint2 o;
        o.x = bf16pair(qx, qy);
        o.y = bf16pair(qz, qw);
        qr[tid + 256 * i] = o;
    }
}

// ---------------------------------------------------------------------------
// Kernel 2: bf16 HMMA GEMM, 256x128 tile, 512 thr (round-12 config: best)
// ---------------------------------------------------------------------------
__device__ __forceinline__ void cp_async16(uint32_t dst, const void* src) {
    asm volatile("cp.async.cg.shared.global [%0], [%1], 16;\n" :: "r"(dst), "l"(src));
}
__device__ __forceinline__ void mma_bf16(float* c, const uint32_t* a, const uint32_t* b) {
    asm volatile(
        "mma.sync.aligned.m16n8k16.row.col.f32.bf16.bf16.f32 "
        "{%0,%1,%2,%3}, {%4,%5,%6,%7}, {%8,%9}, {%0,%1,%2,%3};"
        : "+f"(c[0]), "+f"(c[1]), "+f"(c[2]), "+f"(c[3])
        : "r"(a[0]), "r"(a[1]), "r"(a[2]), "r"(a[3]), "r"(b[0]), "r"(b[1]));
}
__device__ __forceinline__ void ldsm_x4(uint32_t& r0, uint32_t& r1,
                                        uint32_t& r2, uint32_t& r3, uint32_t addr) {
    asm volatile("ldmatrix.sync.aligned.m8n8.x4.shared.b16 {%0,%1,%2,%3}, [%4];"
                 : "=r"(r0), "=r"(r1), "=r"(r2), "=r"(r3) : "r"(addr));
}

__global__ __launch_bounds__(512, 1)
void gemm_kernel(const float* __restrict__ wscale,
                 const float* __restrict__ lora_b,
                 float* __restrict__ out) {
    extern __shared__ __align__(128) char smem[];
    uint32_t sbase = (uint32_t)__cvta_generic_to_shared(smem);

    int tid  = threadIdx.x;
    int wid  = tid >> 5;
    int lane = tid & 31;
    int gid  = lane >> 2;
    int tid4 = lane & 3;
    int wm = wid & 3;          // 4 warps along M (64 rows each)
    int wn = wid >> 2;         // 4 warps along N (32 cols each)
    int bm = blockIdx.y, bn = blockIdx.x;

    const char* Aglob = (const char*)(g_xh + (size_t)(bm * BM) * K_IN);
    const char* Bglob = (const char*)(g_wh + (size_t)(bn * BN) * K_IN);

    int a_row  = ((lane >> 3) & 1) * 8 + (lane & 7);
    int a_koff = (lane >> 4) * 16;
    int b_row  = (lane >> 4) * 8 + (lane & 7);
    int b_koff = ((lane >> 3) & 1) * 16;

    float c[4][4][4];
#pragma unroll
    for (int mf = 0; mf < 4; mf++)
#pragma unroll
        for (int nf = 0; nf < 4; nf++)
#pragma unroll
            for (int i = 0; i < 4; i++) c[mf][nf][i] = 0.f;

#define LOAD_TILE(t)                                                              \
    do {                                                                          \
        int _s  = (t) % STAGES;                                                   \
        int _k0 = (t) * 128;  /* bytes along K */                                 \
        uint32_t _sa = sbase + _s * STAGE_BYTES;                                  \
        uint32_t _sb = _sa + BM * SROW;                                           \
        _Pragma("unroll")                                                         \
        for (int _u = 0; _u < 4; _u++) {                                          \
            int _idx = tid + 512 * _u;                                            \
            int _row = _idx >> 3;                                                 \
            int _ch  = (_idx & 7) * 16;                                           \
            cp_async16(_sa + _row * SROW + _ch,                                   \
                       Aglob + (size_t)_row * K_BYTES + _k0 + _ch);               \
        }                                                                         \
        _Pragma("unroll")                                                         \
        for (int _u = 0; _u < 2; _u++) {                                          \
            int _idx = tid + 512 * _u;                                            \
            int _row = _idx >> 3;                                                 \
            int _ch  = (_idx & 7) * 16;                                           \
            cp_async16(_sb + _row * SROW + _ch,                                   \
                       Bglob + (size_t)_row * K_BYTES + _k0 + _ch);               \
        }                                                                         \
        asm volatile("cp.async.commit_group;\n");                                 \
    } while (0)

    LOAD_TILE(0); LOAD_TILE(1);

    for (int kt = 0; kt < NKT; kt++) {
        asm volatile("cp.async.wait_group 1;\n");
        __syncthreads();

        int buf = kt % STAGES;
        uint32_t aBase = sbase + buf * STAGE_BYTES + (wm * 64 + a_row) * SROW + a_koff;
        uint32_t bBase = sbase + buf * STAGE_BYTES + BM * SROW + (wn * 32 + b_row) * SROW + b_koff;
#pragma unroll
        for (int ks = 0; ks < 4; ks++) {
            int ko = ks * 32;   // 16 bf16 = 32 bytes per mma K-step
            uint32_t a[4][4];
#pragma unroll
            for (int mf = 0; mf < 4; mf++)
                ldsm_x4(a[mf][0], a[mf][1], a[mf][2], a[mf][3],
                        aBase + mf * 16 * SROW + ko);
            // consume B fragments immediately: only 4 B regs live at a time
#pragma unroll
            for (int np = 0; np < 2; np++) {
                uint32_t b0[2], b1[2];
                ldsm_x4(b0[0], b0[1], b1[0], b1[1],
                        bBase + np * 16 * SROW + ko);
#pragma unroll
                for (int mf = 0; mf < 4; mf++) {
                    mma_bf16(c[mf][2 * np + 0], a[mf], b0);
                    mma_bf16(c[mf][2 * np + 1], a[mf], b1);
                }
            }
        }

        if (kt + 2 < NKT) {
            LOAD_TILE(kt + 2);
        } else {
            asm volatile("cp.async.commit_group;\n");
        }
    }
    asm volatile("cp.async.wait_group 0;\n");
    __syncthreads();

    // --- epilogue: reuse smem stage 0 ---
    float* s_xs = (float*)smem;            // [BM]
    float* s_ws = s_xs + BM;               // [BN]
    float* s_xa = s_ws + BN;               // [BM*RANK]
    float* s_lb = s_xa + BM * RANK;        // [BN*RANK]

    if (tid < BM) s_xs[tid] = g_xs[bm * BM + tid];
    if (tid < BN) s_ws[tid] = wscale[bn * BN + tid];
    for (int i = tid; i < BM * RANK / 4; i += 512)
        ((float4*)s_xa)[i] = ((const float4*)(g_xa + (size_t)bm * BM * RANK))[i];
    for (int i = tid; i < BN * RANK / 4; i += 512)
        ((float4*)s_lb)[i] = ((const float4*)(lora_b + (size_t)bn * BN * RANK))[i];
    __syncthreads();

#pragma unroll
    for (int mf = 0; mf < 4; mf++) {
#pragma unroll
        for (int nf = 0; nf < 4; nf++) {
            int rl0 = wm * 64 + mf * 16 + gid;
            int cl  = wn * 32 + nf * 8 + tid4 * 2;
            float ws0 = s_ws[cl], ws1 = s_ws[cl + 1];
#pragma unroll
            for (int h = 0; h < 2; h++) {
                int rl = rl0 + h * 8;
                float xs = s_xs[rl];
                float l0 = 0.f, l1 = 0.f;
#pragma unroll
                for (int r = 0; r < RANK; r++) {
                    float xv = s_xa[rl * RANK + r];
                    l0 = fmaf(xv, s_lb[cl * RANK + r], l0);
                    l1 = fmaf(xv, s_lb[(cl + 1) * RANK + r], l1);
                }
                float o0 = c[mf][nf][h * 2 + 0] * xs * ws0 + l0;
                float o1 = c[mf][nf][h * 2 + 1] * xs * ws1 + l1;
                size_t grow = (size_t)(bm * BM + rl);
                int    gcol = bn * BN + cl;
                *(float2*)(out + grow * N_OUT + gcol) = make_float2(o0, o1);
            }
        }
    }
}

// ---------------------------------------------------------------------------
extern "C" void kernel_launch(void* const* d_in, const int* in_sizes, int n_in,
                              void* d_out, int out_size) {
    const float*  x      = (const float*)d_in[0];
    const void*   w_raw  = d_in[1];
    const float*  wscale = (const float*)d_in[2];
    const float*  lora_a = (const float*)d_in[3];
    const float*  lora_b = (const float*)d_in[4];
    float* out = (float*)d_out;

    int T = in_sizes[0] / K_IN;  // 8192

    cudaFuncSetAttribute(gemm_kernel,
                         cudaFuncAttributeMaxDynamicSharedMemorySize, SMEM_TOTAL);

    prework_kernel<<<2 * T, 256>>>(x, lora_a, w_raw);
    dim3 g3(N_OUT / BN, T / BM);
    gemm_kernel<<<g3, 512, SMEM_TOTAL>>>(wscale, lora_b, out);
}